// round 5
// baseline (speedup 1.0000x reference)
#include <cuda_runtime.h>
#include <cstdint>

// Problem constants
#define BATCH 2
#define CHAN  128
#define NGRP  16
#define CPG   8
#define HH    64
#define WW    64
#define HW    (HH*WW)
#define NP    81
#define NDIL  4
#define NPHW  (NP*HW)

// Conv tiling: 8 rows x 64 wide per block; thread = 8 rows x 1 col x 4 gout
#define TILE_H 8
#define SIN_H  (TILE_H + 2)          // 10
#define SIN_W  (WW + 2)              // 66
#define SLAB   (3 * SIN_H * SIN_W)   // 1980 floats per gin slab
#define SLAB_LD 8                    // ceil(1980/256)
#define NBUF   4                     // slab ring depth
#define SW_ELEMS (NGRP * NGRP * 27)  // 6912

// Scratch cost volume: [dil*b][g][disp][h][w] ~170MB
__device__ float g_cost[(size_t)NDIL * BATCH * NGRP * NPHW];

// ---- packed fp32x2 helpers ----
__device__ __forceinline__ unsigned long long pack_dup(float v) {
    unsigned long long r;
    asm("mov.b64 %0, {%1, %1};" : "=l"(r) : "f"(v));
    return r;
}
__device__ __forceinline__ unsigned long long ffma2(
    unsigned long long a, unsigned long long b, unsigned long long c) {
    unsigned long long d;
    asm("fma.rn.f32x2 %0, %1, %2, %3;" : "=l"(d) : "l"(a), "l"(b), "l"(c));
    return d;
}
__device__ __forceinline__ uint32_t smem_u32(const void* p) {
    uint32_t a;
    asm("{ .reg .u64 t; cvta.to.shared.u64 t, %1; cvt.u32.u64 %0, t; }"
        : "=r"(a) : "l"(p));
    return a;
}
__device__ __forceinline__ void cp_async4(uint32_t dst, const float* src, int sz) {
    asm volatile("cp.async.ca.shared.global [%0], [%1], 4, %2;"
                 :: "r"(dst), "l"(src), "r"(sz));
}

// ---------------------------------------------------------------------------
// Kernel 1: grouped windowed correlation + leaky ReLU(0.1)
// ---------------------------------------------------------------------------
__global__ void corr_kernel(const float* __restrict__ x,
                            const float* __restrict__ nb) {
    const int w  = threadIdx.x;
    const int h  = blockIdx.x * 4 + threadIdx.y;
    const int g  = blockIdx.y;
    const int zb = blockIdx.z;
    const int b  = zb & 1;
    const int dil = 1 << (zb >> 1);

    float a1[CPG];
#pragma unroll
    for (int c = 0; c < CPG; c++)
        a1[c] = x[(size_t)(b * CHAN + c * NGRP + g) * HW + h * WW + w];

    const float* __restrict__ x2b = nb + (size_t)b * CHAN * HW;
    float* __restrict__ outp =
        g_cost + ((size_t)(zb * NGRP + g) * NP) * HW + h * WW + w;

#pragma unroll 1
    for (int di = 0; di < 9; di++) {
        const int y = h + (di - 4) * dil;
        const bool yok = ((unsigned)y < HH);
#pragma unroll 1
        for (int dj = 0; dj < 9; dj++) {
            const int xw = w + (dj - 4) * dil;
            float s = 0.f;
            if (yok && (unsigned)xw < WW) {
                const int off = y * WW + xw;
#pragma unroll
                for (int c = 0; c < CPG; c++)
                    s += a1[c] * x2b[(size_t)(c * NGRP + g) * HW + off];
            }
            s = (s > 0.f) ? s : 0.1f * s;
            outp[(size_t)(di * 9 + dj) * HW] = s;
        }
    }
}

// ---------------------------------------------------------------------------
// helper: issue one gin slab via cp.async (zfill for halo)
// ---------------------------------------------------------------------------
__device__ __forceinline__ void stage_slab(uint32_t dst_base,
                                           const float* __restrict__ src,
                                           int tid, int d, int h0) {
#pragma unroll
    for (int k = 0; k < SLAB_LD; k++) {
        int i = tid + k * 256;
        if (i < SLAB) {
            int kd = i / (SIN_H * SIN_W);
            int r  = i - kd * (SIN_H * SIN_W);
            int hi = r / SIN_W;
            int wi = r - hi * SIN_W;
            int dg = d + kd - 1;
            int hg = h0 + hi - 1;
            int wg = wi - 1;
            bool ok = ((unsigned)dg < NP) & ((unsigned)hg < HH) &
                      ((unsigned)wg < WW);
            int ofs = ok ? (dg * HW + hg * WW + wg) : 0;
            cp_async4(dst_base + (uint32_t)i * 4, src + ofs, ok ? 4 : 0);
        }
    }
    asm volatile("cp.async.commit_group;");
}

// ---------------------------------------------------------------------------
// Kernel 2: 3x3x3 grouped conv (16->16) + bias + BN + ReLU
// thread = 8 rows x 1 col x 4 gout; f32x2 accs; ring-4 cp.async; 3 CTAs/SM
// grid: (1, HH/TILE_H=8, NDIL*BATCH*NP=648), block (64,4)=256
// ---------------------------------------------------------------------------
__global__ void __launch_bounds__(256, 3)
conv_kernel(const float* __restrict__ conv_w,
            const float* __restrict__ conv_b,
            const float* __restrict__ bn_gamma,
            const float* __restrict__ bn_beta,
            const float* __restrict__ bn_mean,
            const float* __restrict__ bn_var,
            float* __restrict__ out) {
    extern __shared__ float sm[];
    float* s_in = sm;                    // [NBUF][SLAB]
    float* s_w  = sm + NBUF * SLAB;      // [gin*27+tap][16 gout]
    float* s_sc = s_w + SW_ELEMS;
    float* s_sh = s_sc + NGRP;

    const int tx  = threadIdx.x;         // 0..63 : column
    const int q   = threadIdx.y;         // 0..3  : gout quarter
    const int tid = q * 64 + tx;
    const int zb  = blockIdx.z;
    const int dil_idx = zb / (BATCH * NP);
    const int rem = zb % (BATCH * NP);
    const int b   = rem / NP;
    const int d   = rem % NP;
    const int h0  = blockIdx.y * TILE_H;

    const float* __restrict__ costz =
        g_cost + (size_t)(dil_idx * BATCH + b) * NGRP * NPHW;
    uint32_t s_in_addr = smem_u32(s_in);

    // Stage weights transposed: [gin*27+tap][gout]
    const float* __restrict__ wsrc = conv_w + (size_t)dil_idx * SW_ELEMS;
    for (int i = tid; i < SW_ELEMS; i += 256) {
        int gout = i / (NGRP * 27);
        int gt   = i - gout * (NGRP * 27);
        s_w[gt * NGRP + gout] = wsrc[i];
    }
    if (tid < NGRP) {
        int gi = dil_idx * NGRP + tid;
        float inv = bn_gamma[gi] * rsqrtf(bn_var[gi] + 1e-5f);
        s_sc[tid] = inv;
        s_sh[tid] = (conv_b[gi] - bn_mean[gi]) * inv + bn_beta[gi];
    }

    // Prologue: stage slabs gin=0,1
    stage_slab(s_in_addr, costz, tid, d, h0);
    stage_slab(s_in_addr + SLAB * 4, costz + NPHW, tid, d, h0);

    // Accumulators: 8 rows x 4 gout (2 f32x2 pairs per row)
    unsigned long long acc[8][2];
#pragma unroll
    for (int i = 0; i < 8; i++) { acc[i][0] = 0ull; acc[i][1] = 0ull; }

#pragma unroll 1
    for (int gin = 0; gin < NGRP; gin++) {
        if (gin + 2 < NGRP) {
            stage_slab(s_in_addr + (uint32_t)(((gin + 2) & 3) * SLAB) * 4,
                       costz + (size_t)(gin + 2) * NPHW, tid, d, h0);
            asm volatile("cp.async.wait_group 2;");
        } else if (gin + 2 == NGRP) {
            asm volatile("cp.async.wait_group 1;");
        } else {
            asm volatile("cp.async.wait_group 0;");
        }
        __syncthreads();   // single barrier per gin

        const float* __restrict__ in_g = s_in + (gin & 3) * SLAB + tx;
        const float* __restrict__ w_g  = s_w + gin * 27 * NGRP + q * 4;

#pragma unroll
        for (int kd = 0; kd < 3; kd++) {
#pragma unroll
            for (int kw = 0; kw < 3; kw++) {
                // 10 padded rows cover kh-rotation for all 8 output rows
                unsigned long long vv[10];
#pragma unroll
                for (int j = 0; j < 10; j++)
                    vv[j] = pack_dup(in_g[kd * (SIN_H * SIN_W) + j * SIN_W + kw]);
#pragma unroll
                for (int kh = 0; kh < 3; kh++) {
                    const ulonglong2 w = *(const ulonglong2*)(
                        w_g + (kd * 9 + kh * 3 + kw) * NGRP);
#pragma unroll
                    for (int i = 0; i < 8; i++) {
                        const unsigned long long v = vv[i + kh];
                        acc[i][0] = ffma2(v, w.x, acc[i][0]);
                        acc[i][1] = ffma2(v, w.y, acc[i][1]);
                    }
                }
            }
        }
    }

    // Epilogue: BN scale/shift + ReLU (this thread's 4 gouts)
    float sc[4], sh[4];
#pragma unroll
    for (int g = 0; g < 4; g++) {
        sc[g] = s_sc[q * 4 + g];
        sh[g] = s_sh[q * 4 + g];
    }

    const size_t ob0 =
        ((size_t)(b * (NDIL * NGRP) + dil_idx * NGRP + q * 4) * NP + d) * HW + tx;
#pragma unroll
    for (int i = 0; i < 8; i++) {
        const size_t ob = ob0 + (size_t)(h0 + i) * WW;
#pragma unroll
        for (int p = 0; p < 2; p++) {
            float lo, hi;
            asm("mov.b64 {%0, %1}, %2;" : "=f"(lo), "=f"(hi) : "l"(acc[i][p]));
            out[ob + (size_t)(2 * p) * NPHW] =
                fmaxf(lo * sc[2 * p] + sh[2 * p], 0.f);
            out[ob + (size_t)(2 * p + 1) * NPHW] =
                fmaxf(hi * sc[2 * p + 1] + sh[2 * p + 1], 0.f);
        }
    }
}

#define SMEM_BYTES ((NBUF * SLAB + SW_ELEMS + 2 * NGRP + 16) * 4)

// ---------------------------------------------------------------------------
extern "C" void kernel_launch(void* const* d_in, const int* in_sizes, int n_in,
                              void* d_out, int out_size) {
    const float* x  = (const float*)d_in[0];
    const float* nb = (const float*)d_in[1];
    const float* cw = (const float*)d_in[2];
    const float* cb = (const float*)d_in[3];
    const float* gm = (const float*)d_in[4];
    const float* bt = (const float*)d_in[5];
    const float* mn = (const float*)d_in[6];
    const float* vr = (const float*)d_in[7];
    float* out = (float*)d_out;

    dim3 cb1(64, 4);
    dim3 cg1(HH / 4, NGRP, NDIL * BATCH);
    corr_kernel<<<cg1, cb1>>>(x, nb);

    cudaFuncSetAttribute(conv_kernel,
                         cudaFuncAttributeMaxDynamicSharedMemorySize,
                         SMEM_BYTES);
    dim3 cg2(1, HH / TILE_H, NDIL * BATCH * NP);
    conv_kernel<<<cg2, dim3(64, 4), SMEM_BYTES>>>(cw, cb, gm, bt, mn, vr, out);
}

// round 7
// speedup vs baseline: 2.3272x; 2.3272x over previous
#include <cuda_runtime.h>
#include <cstdint>

// Problem constants
#define BATCH 2
#define CHAN  128
#define NGRP  16
#define CPG   8
#define HH    64
#define WW    64
#define HW    (HH*WW)
#define NP    81
#define NDIL  4
#define NPHW  (NP*HW)

// Scratch cost volume (tf32-rounded fp32): [dil*b][g][d][h][w] ~170MB
__device__ float g_cost[(size_t)NDIL * BATCH * NGRP * NPHW];

// Conv slab geometry: per d-slice [gin(16)][row(4)][col(72)] + 8 pad
//  - col 4..67 hold image cols 0..63; col 3 / 68 are the (zero) -1/64 halo
//  - GPITCH = 296 floats == 8 (mod 32)  ->  B-fragment LDS is conflict-free
#define RPITCH 72
#define GPITCH 296
#define SLABF  (NGRP * GPITCH)    // 4736 floats per slice
#define NRING  4
#define NCHUNK 54                 // 27 taps x 2 gin-halves (K=432 in k8 steps)
#define WFRAGF (NCHUNK * 32 * 4)  // fragment-packed weights: 6912 floats
#define SMEM_BYTES ((NRING * SLABF + WFRAGF + 64) * 4)

// ---------------- helpers ----------------
__device__ __forceinline__ uint32_t smem_u32(const void* p) {
    uint32_t a;
    asm("{ .reg .u64 t; cvta.to.shared.u64 t, %1; cvt.u32.u64 %0, t; }"
        : "=r"(a) : "l"(p));
    return a;
}
__device__ __forceinline__ void cp_async16(uint32_t dst, const float* src) {
    asm volatile("cp.async.ca.shared.global [%0], [%1], 16;"
                 :: "r"(dst), "l"(src));
}
__device__ __forceinline__ float to_tf32(float v) {
    uint32_t t;
    asm("cvt.rna.tf32.f32 %0, %1;" : "=r"(t) : "f"(v));
    return __uint_as_float(t);
}
__device__ __forceinline__ void mma_tf32(float c[4], const uint32_t a[4],
                                         uint32_t b0, uint32_t b1) {
    asm volatile(
        "mma.sync.aligned.m16n8k8.row.col.f32.tf32.tf32.f32 "
        "{%0,%1,%2,%3}, {%4,%5,%6,%7}, {%8,%9}, {%0,%1,%2,%3};"
        : "+f"(c[0]), "+f"(c[1]), "+f"(c[2]), "+f"(c[3])
        : "r"(a[0]), "r"(a[1]), "r"(a[2]), "r"(a[3]), "r"(b0), "r"(b1));
}

// ---------------------------------------------------------------------------
// Kernel 1: grouped windowed correlation + leaky ReLU(0.1), tf32-rounded out
// ---------------------------------------------------------------------------
__global__ void corr_kernel(const float* __restrict__ x,
                            const float* __restrict__ nb) {
    const int w  = threadIdx.x;
    const int h  = blockIdx.x * 4 + threadIdx.y;
    const int g  = blockIdx.y;
    const int zb = blockIdx.z;
    const int b  = zb & 1;
    const int dil = 1 << (zb >> 1);

    float a1[CPG];
#pragma unroll
    for (int c = 0; c < CPG; c++)
        a1[c] = x[(size_t)(b * CHAN + c * NGRP + g) * HW + h * WW + w];

    const float* __restrict__ x2b = nb + (size_t)b * CHAN * HW;
    float* __restrict__ outp =
        g_cost + ((size_t)(zb * NGRP + g) * NP) * HW + h * WW + w;

#pragma unroll 1
    for (int di = 0; di < 9; di++) {
        const int y = h + (di - 4) * dil;
        const bool yok = ((unsigned)y < HH);
#pragma unroll 1
        for (int dj = 0; dj < 9; dj++) {
            const int xw = w + (dj - 4) * dil;
            float s = 0.f;
            if (yok && (unsigned)xw < WW) {
                const int off = y * WW + xw;
#pragma unroll
                for (int c = 0; c < CPG; c++)
                    s += a1[c] * x2b[(size_t)(c * NGRP + g) * HW + off];
            }
            s = (s > 0.f) ? s : 0.1f * s;        // leaky relu
            outp[(size_t)(di * 9 + dj) * HW] = to_tf32(s);
        }
    }
}

// ---------------------------------------------------------------------------
// Kernel 2: 3x3x3 grouped conv (16->16) via warp-level tf32 mma.sync
//   D[gout(16=M), px(8=N)] += W[gout, k] * A[k, px], K = 432 (54 k8-chunks)
// CTA = 128 threads (4 warps), tile = 2 rows x 64 cols; warp = 32 px (4 n-chunks)
// grid = (32 h-strips, 8 = dil*batch); loop d = 0..80 with ring-4 cp.async slabs
// ---------------------------------------------------------------------------
__global__ void __launch_bounds__(128, 2)
conv_kernel(const float* __restrict__ conv_w,
            const float* __restrict__ conv_b,
            const float* __restrict__ bn_gamma,
            const float* __restrict__ bn_beta,
            const float* __restrict__ bn_mean,
            const float* __restrict__ bn_var,
            float* __restrict__ out) {
    extern __shared__ float sm[];
    float* s_slab = sm;                     // [NRING][SLABF]
    float* s_wf   = sm + NRING * SLABF;     // fragment-packed weights
    float* s_sc   = s_wf + WFRAGF;          // [16]
    float* s_sh   = s_sc + 16;              // [16]

    const int tid  = threadIdx.x;
    const int lane = tid & 31;
    const int wid  = tid >> 5;              // 0..3
    const int zb   = blockIdx.y;            // dil*2 + b
    const int dil_idx = zb >> 1;
    const int b    = zb & 1;
    const int h0   = blockIdx.x * 2;        // 2-row strip
    const int wr   = wid >> 1;              // warp row within strip (0/1)
    const int wc   = (wid & 1) * 32;        // warp col base (0/32)

    const float* __restrict__ costz = g_cost + (size_t)zb * NGRP * NPHW;

    // --- zero slab ring (halo pads & out-of-image rows stay zero forever) ---
    for (int i = tid; i < NRING * SLABF; i += 128) s_slab[i] = 0.f;

    // --- pack weights into mma A-fragment order: wf[chunk][lane] = float4 ---
    // chunk = tap*2 + half ; A row=gout, col k=gin(half*8 + j)
    // a0=W[g0][j], a1=W[g0+8][j], a2=W[g0][j+4], a3=W[g0+8][j+4]
    {
        const float* __restrict__ wb = conv_w + (size_t)dil_idx * 16 * 16 * 27;
        for (int i = tid; i < NCHUNK * 32; i += 128) {
            int chunk = i >> 5, l = i & 31;
            int tap = chunk >> 1, half = chunk & 1;
            int g0 = l >> 2, j = l & 3;
            int gin0 = half * 8 + j;
            float4 v;
            v.x = to_tf32(wb[((g0)     * 16 + gin0)     * 27 + tap]);
            v.y = to_tf32(wb[((g0 + 8) * 16 + gin0)     * 27 + tap]);
            v.z = to_tf32(wb[((g0)     * 16 + gin0 + 4) * 27 + tap]);
            v.w = to_tf32(wb[((g0 + 8) * 16 + gin0 + 4) * 27 + tap]);
            ((float4*)s_wf)[i] = v;
        }
    }
    // --- fold conv bias + BN ---
    if (tid < NGRP) {
        int gi = dil_idx * NGRP + tid;
        float inv = bn_gamma[gi] * rsqrtf(bn_var[gi] + 1e-5f);
        s_sc[tid] = inv;
        s_sh[tid] = (conv_b[gi] - bn_mean[gi]) * inv + bn_beta[gi];
    }
    __syncthreads();   // zeros + weights committed before staging/compute

    const uint32_t slab_base = smem_u32(s_slab);

    // stage one d-slice into ring slot (16B cp.async, cols 0..63 -> 4..67)
    auto stage = [&](int s) {
        uint32_t dslot = slab_base + (uint32_t)((s & 3) * SLABF) * 4;
        const float* __restrict__ src0 = costz + (size_t)s * HW;
#pragma unroll
        for (int k = 0; k < 8; k++) {
            int o = tid + k * 128;            // 1024 ops: g(16) x r(4) x seg(16)
            int g = o >> 6, r = (o >> 4) & 3, seg = o & 15;
            int hg = h0 - 1 + r;
            if ((unsigned)hg < HH)
                cp_async16(dslot + (uint32_t)(g * GPITCH + r * RPITCH + 4 +
                                              seg * 4) * 4,
                           src0 + (size_t)g * NPHW + hg * WW + seg * 4);
        }
        asm volatile("cp.async.commit_group;");
    };

    stage(0);
    stage(1);

    // per-thread B fragment base: k-row = lane%4 (gin), n-col = lane/4 (px)
    const int bq = (lane & 3) * GPITCH + (lane >> 2);
    const int g0 = lane >> 2;
    const float sc0 = s_sc[g0], sh0 = s_sh[g0];
    const float sc8 = s_sc[g0 + 8], sh8 = s_sh[g0 + 8];
    const uint4* __restrict__ wf4 = (const uint4*)s_wf;

    const size_t obase =
        ((size_t)(b * (NDIL * NGRP) + dil_idx * NGRP) * NP) * HW +
        (size_t)(h0 + wr) * WW;

#pragma unroll 1
    for (int d = 0; d < NP; d++) {
        if (d + 2 < NP) {
            stage(d + 2);
            asm volatile("cp.async.wait_group 1;");
        } else {
            asm volatile("cp.async.wait_group 0;");
        }
        __syncthreads();   // slices d-1..d+1 visible

        float acc[4][4];
#pragma unroll
        for (int nc = 0; nc < 4; nc++)
#pragma unroll
            for (int j = 0; j < 4; j++) acc[nc][j] = 0.f;

#pragma unroll
        for (int kd = 0; kd < 3; kd++) {
            const int s = d + kd - 1;
            if ((unsigned)s >= NP) continue;
            const float* __restrict__ slot = s_slab + (s & 3) * SLABF;
#pragma unroll
            for (int kh = 0; kh < 3; kh++) {
#pragma unroll
                for (int kw = 0; kw < 3; kw++) {
#pragma unroll
                    for (int half = 0; half < 2; half++) {
                        const int chunk = (kd * 9 + kh * 3 + kw) * 2 + half;
                        uint4 av = wf4[chunk * 32 + lane];
                        uint32_t A[4] = {av.x, av.y, av.z, av.w};
                        const float* baddr = slot + half * 8 * GPITCH +
                                             (wr + kh) * RPITCH +
                                             (3 + wc + kw) + bq;
#pragma unroll
                        for (int nc = 0; nc < 4; nc++) {
                            uint32_t b0 = __float_as_uint(baddr[nc * 8]);
                            uint32_t b1 = __float_as_uint(
                                baddr[nc * 8 + 4 * GPITCH]);
                            mma_tf32(acc[nc], A, b0, b1);
                        }
                    }
                }
            }
        }
        __syncthreads();   // all reads of slice d-1 done before next stage

        // epilogue: BN scale/shift + ReLU; c0/c1 adjacent px -> float2 stores
        const size_t ob = obase + (size_t)d * HW;
#pragma unroll
        for (int nc = 0; nc < 4; nc++) {
            const int px = wc + nc * 8 + (lane & 3) * 2;
            float2 v0, v1;
            v0.x = fmaxf(acc[nc][0] * sc0 + sh0, 0.f);
            v0.y = fmaxf(acc[nc][1] * sc0 + sh0, 0.f);
            v1.x = fmaxf(acc[nc][2] * sc8 + sh8, 0.f);
            v1.y = fmaxf(acc[nc][3] * sc8 + sh8, 0.f);
            *(float2*)&out[ob + (size_t)g0 * NPHW + px] = v0;
            *(float2*)&out[ob + (size_t)(g0 + 8) * NPHW + px] = v1;
        }
    }
}

// ---------------------------------------------------------------------------
extern "C" void kernel_launch(void* const* d_in, const int* in_sizes, int n_in,
                              void* d_out, int out_size) {
    const float* x  = (const float*)d_in[0];
    const float* nb = (const float*)d_in[1];
    const float* cw = (const float*)d_in[2];
    const float* cb = (const float*)d_in[3];
    const float* gm = (const float*)d_in[4];
    const float* bt = (const float*)d_in[5];
    const float* mn = (const float*)d_in[6];
    const float* vr = (const float*)d_in[7];
    float* out = (float*)d_out;

    dim3 cb1(64, 4);
    dim3 cg1(HH / 4, NGRP, NDIL * BATCH);
    corr_kernel<<<cg1, cb1>>>(x, nb);

    cudaFuncSetAttribute(conv_kernel,
                         cudaFuncAttributeMaxDynamicSharedMemorySize,
                         SMEM_BYTES);
    dim3 cg2(HH / 2, NDIL * BATCH);    // 32 strips x 8
    conv_kernel<<<cg2, 128, SMEM_BYTES>>>(cw, cb, gm, bt, mn, vr, out);
}

// round 8
// speedup vs baseline: 2.8230x; 1.2131x over previous
#include <cuda_runtime.h>
#include <cstdint>

// Problem constants
#define BATCH 2
#define CHAN  128
#define NGRP  16
#define CPG   8
#define HH    64
#define WW    64
#define HW    (HH*WW)
#define NP    81
#define NDIL  4
#define NPHW  (NP*HW)

// Scratch cost volume (tf32-rounded fp32): [dil*b][g][d][h][w] ~170MB
__device__ float g_cost[(size_t)NDIL * BATCH * NGRP * NPHW];

// Conv slab geometry: per d-slice [gin(16)][row(4)][col(72)] + 8 pad
//  GPITCH = 296 == 8 (mod 32) -> B-fragment LDS is bank-conflict-free
#define RPITCH 72
#define GPITCH 296
#define SLABF  (NGRP * GPITCH)    // 4736 floats per slice
#define NRING  2
#define NCHUNK 54                 // 27 taps x 2 gin-halves
#define WFRAGF (NCHUNK * 32 * 4)  // fragment-packed weights: 6912 floats
#define SMEM_BYTES ((NRING * SLABF + WFRAGF + 64) * 4)

// ---------------- helpers ----------------
__device__ __forceinline__ uint32_t smem_u32(const void* p) {
    uint32_t a;
    asm("{ .reg .u64 t; cvta.to.shared.u64 t, %1; cvt.u32.u64 %0, t; }"
        : "=r"(a) : "l"(p));
    return a;
}
__device__ __forceinline__ void cp_async16(uint32_t dst, const float* src) {
    asm volatile("cp.async.ca.shared.global [%0], [%1], 16;"
                 :: "r"(dst), "l"(src));
}
__device__ __forceinline__ float to_tf32(float v) {
    uint32_t t;
    asm("cvt.rna.tf32.f32 %0, %1;" : "=r"(t) : "f"(v));
    return __uint_as_float(t);
}
__device__ __forceinline__ void mma_tf32(float c[4], const uint32_t a[4],
                                         uint32_t b0, uint32_t b1) {
    asm volatile(
        "mma.sync.aligned.m16n8k8.row.col.f32.tf32.tf32.f32 "
        "{%0,%1,%2,%3}, {%4,%5,%6,%7}, {%8,%9}, {%0,%1,%2,%3};"
        : "+f"(c[0]), "+f"(c[1]), "+f"(c[2]), "+f"(c[3])
        : "r"(a[0]), "r"(a[1]), "r"(a[2]), "r"(a[3]), "r"(b0), "r"(b1));
}

// ---------------------------------------------------------------------------
// Kernel 1: grouped windowed correlation + leaky ReLU(0.1), tf32-rounded out
// ---------------------------------------------------------------------------
__global__ void corr_kernel(const float* __restrict__ x,
                            const float* __restrict__ nb) {
    const int w  = threadIdx.x;
    const int h  = blockIdx.x * 4 + threadIdx.y;
    const int g  = blockIdx.y;
    const int zb = blockIdx.z;
    const int b  = zb & 1;
    const int dil = 1 << (zb >> 1);

    float a1[CPG];
#pragma unroll
    for (int c = 0; c < CPG; c++)
        a1[c] = x[(size_t)(b * CHAN + c * NGRP + g) * HW + h * WW + w];

    const float* __restrict__ x2b = nb + (size_t)b * CHAN * HW;
    float* __restrict__ outp =
        g_cost + ((size_t)(zb * NGRP + g) * NP) * HW + h * WW + w;

#pragma unroll 1
    for (int di = 0; di < 9; di++) {
        const int y = h + (di - 4) * dil;
        const bool yok = ((unsigned)y < HH);
#pragma unroll 1
        for (int dj = 0; dj < 9; dj++) {
            const int xw = w + (dj - 4) * dil;
            float s = 0.f;
            if (yok && (unsigned)xw < WW) {
                const int off = y * WW + xw;
#pragma unroll
                for (int c = 0; c < CPG; c++)
                    s += a1[c] * x2b[(size_t)(c * NGRP + g) * HW + off];
            }
            s = (s > 0.f) ? s : 0.1f * s;
            outp[(size_t)(di * 9 + dj) * HW] = to_tf32(s);
        }
    }
}

// ---------------------------------------------------------------------------
// Kernel 2: 3x3x3 grouped conv via tf32 mma.sync with slice-streaming:
// each cost slice s is loaded ONCE and contributes (via 3 weight kd-sets) to
// the three rotating accumulators d = s+1 (A), s (B), s-1 (C).
// CTA = 128 thr, tile 2 rows x 64 cols; grid (32 strips, 8 zb, 2 d-segments)
// ---------------------------------------------------------------------------
__global__ void __launch_bounds__(128, 3)
conv_kernel(const float* __restrict__ conv_w,
            const float* __restrict__ conv_b,
            const float* __restrict__ bn_gamma,
            const float* __restrict__ bn_beta,
            const float* __restrict__ bn_mean,
            const float* __restrict__ bn_var,
            float* __restrict__ out) {
    extern __shared__ float sm[];
    float* s_slab = sm;                     // [NRING][SLABF]
    float* s_wf   = sm + NRING * SLABF;     // fragment-packed weights
    float* s_sc   = s_wf + WFRAGF;
    float* s_sh   = s_sc + 16;

    const int tid  = threadIdx.x;
    const int lane = tid & 31;
    const int wid  = tid >> 5;
    const int zb   = blockIdx.y;
    const int dil_idx = zb >> 1;
    const int b    = zb & 1;
    const int h0   = blockIdx.x * 2;
    const int wr   = wid >> 1;
    const int wc   = (wid & 1) * 32;
    const int dseg = blockIdx.z;
    const int d0   = dseg ? 41 : 0;
    const int dend = dseg ? 81 : 41;        // [d0, dend)

    const float* __restrict__ costz = g_cost + (size_t)zb * NGRP * NPHW;

    // zero slab ring (halo/border stays zero)
    for (int i = tid; i < NRING * SLABF; i += 128) s_slab[i] = 0.f;

    // pack weights into mma A-fragment order
    {
        const float* __restrict__ wb = conv_w + (size_t)dil_idx * 16 * 16 * 27;
        for (int i = tid; i < NCHUNK * 32; i += 128) {
            int chunk = i >> 5, l = i & 31;
            int tap = chunk >> 1, half = chunk & 1;
            int g0 = l >> 2, j = l & 3;
            int gin0 = half * 8 + j;
            float4 v;
            v.x = to_tf32(wb[((g0)     * 16 + gin0)     * 27 + tap]);
            v.y = to_tf32(wb[((g0 + 8) * 16 + gin0)     * 27 + tap]);
            v.z = to_tf32(wb[((g0)     * 16 + gin0 + 4) * 27 + tap]);
            v.w = to_tf32(wb[((g0 + 8) * 16 + gin0 + 4) * 27 + tap]);
            ((float4*)s_wf)[i] = v;
        }
    }
    if (tid < NGRP) {
        int gi = dil_idx * NGRP + tid;
        float inv = bn_gamma[gi] * rsqrtf(bn_var[gi] + 1e-5f);
        s_sc[tid] = inv;
        s_sh[tid] = (conv_b[gi] - bn_mean[gi]) * inv + bn_beta[gi];
    }
    __syncthreads();

    const uint32_t slab_base = smem_u32(s_slab);
    auto stage = [&](int s) {
        uint32_t dslot = slab_base + (uint32_t)((s & 1) * SLABF) * 4;
        const float* __restrict__ src0 = costz + (size_t)s * HW;
#pragma unroll
        for (int k = 0; k < 8; k++) {
            int o = tid + k * 128;
            int g = o >> 6, r = (o >> 4) & 3, seg = o & 15;
            int hg = h0 - 1 + r;
            if ((unsigned)hg < HH)
                cp_async16(dslot + (uint32_t)(g * GPITCH + r * RPITCH + 4 +
                                              seg * 4) * 4,
                           src0 + (size_t)g * NPHW + hg * WW + seg * 4);
        }
        asm volatile("cp.async.commit_group;");
    };

    const int bq = (lane & 3) * GPITCH + (lane >> 2);
    const int g0 = lane >> 2;
    const float sc0 = s_sc[g0], sh0 = s_sh[g0];
    const float sc8 = s_sc[g0 + 8], sh8 = s_sh[g0 + 8];
    const uint4* __restrict__ wf4 = (const uint4*)s_wf;

    // three rotating accumulator sets: A = d=s+1, B = d=s, C = d=s-1
    float accA[4][4], accB[4][4], accC[4][4];
#pragma unroll
    for (int nc = 0; nc < 4; nc++)
#pragma unroll
        for (int j = 0; j < 4; j++) {
            accA[nc][j] = 0.f; accB[nc][j] = 0.f; accC[nc][j] = 0.f;
        }

    // compute body: slice -> 3 accumulator sets (kd selected by validity)
    auto compute = [&](const float* slot, bool do0, bool do1, bool do2) {
#pragma unroll
        for (int kh = 0; kh < 3; kh++) {
#pragma unroll
            for (int kw = 0; kw < 3; kw++) {
#pragma unroll
                for (int half = 0; half < 2; half++) {
                    const float* baddr = slot + half * 8 * GPITCH +
                                         (wr + kh) * RPITCH +
                                         (3 + wc + kw) + bq;
                    uint32_t B0[4], B1[4];
#pragma unroll
                    for (int nc = 0; nc < 4; nc++) {
                        B0[nc] = __float_as_uint(baddr[nc * 8]);
                        B1[nc] = __float_as_uint(baddr[nc * 8 + 4 * GPITCH]);
                    }
                    const int t2 = (kh * 3 + kw) * 2 + half;
                    if (do0) {
                        uint4 av = wf4[t2 * 32 + lane];          // kd = 0
                        uint32_t A[4] = {av.x, av.y, av.z, av.w};
#pragma unroll
                        for (int nc = 0; nc < 4; nc++)
                            mma_tf32(accA[nc], A, B0[nc], B1[nc]);
                    }
                    if (do1) {
                        uint4 av = wf4[(18 + t2) * 32 + lane];   // kd = 1
                        uint32_t A[4] = {av.x, av.y, av.z, av.w};
#pragma unroll
                        for (int nc = 0; nc < 4; nc++)
                            mma_tf32(accB[nc], A, B0[nc], B1[nc]);
                    }
                    if (do2) {
                        uint4 av = wf4[(36 + t2) * 32 + lane];   // kd = 2
                        uint32_t A[4] = {av.x, av.y, av.z, av.w};
#pragma unroll
                        for (int nc = 0; nc < 4; nc++)
                            mma_tf32(accC[nc], A, B0[nc], B1[nc]);
                    }
                }
            }
        }
    };

    const size_t obase =
        ((size_t)(b * (NDIL * NGRP) + dil_idx * NGRP) * NP) * HW +
        (size_t)(h0 + wr) * WW;
    auto writeout = [&](int d, float a[4][4]) {
        const size_t ob = obase + (size_t)d * HW;
#pragma unroll
        for (int nc = 0; nc < 4; nc++) {
            const int px = wc + nc * 8 + (lane & 3) * 2;
            float2 v0, v1;
            v0.x = fmaxf(a[nc][0] * sc0 + sh0, 0.f);
            v0.y = fmaxf(a[nc][1] * sc0 + sh0, 0.f);
            v1.x = fmaxf(a[nc][2] * sc8 + sh8, 0.f);
            v1.y = fmaxf(a[nc][3] * sc8 + sh8, 0.f);
            *(float2*)&out[ob + (size_t)g0 * NPHW + px] = v0;
            *(float2*)&out[ob + (size_t)(g0 + 8) * NPHW + px] = v1;
        }
    };

    const int s_lo = (d0 > 0) ? d0 - 1 : 0;
    const int s_hi = (dend < NP) ? dend : NP - 1;   // inclusive

    stage(s_lo);
    stage(s_lo + 1);

#pragma unroll 1
    for (int s = s_lo; s <= s_hi; s++) {
        if (s < s_hi) asm volatile("cp.async.wait_group 1;");
        else          asm volatile("cp.async.wait_group 0;");
        __syncthreads();

        const float* slot = s_slab + (s & 1) * SLABF;
        // kd valid iff d = s+1-kd in [d0, dend)
        const bool do0 = (s + 1 >= d0) && (s + 1 < dend);
        const bool do1 = (s >= d0) && (s < dend);
        const bool do2 = (s - 1 >= d0);              // s-1 < dend always
        if (do0 && do1 && do2)
            compute(slot, true, true, true);          // branch-free hot path
        else
            compute(slot, do0, do1, do2);

        __syncthreads();          // slot (s) reads done before staging s+2
        if (s + 2 <= s_hi) stage(s + 2);

        if (s > d0) writeout(s - 1, accC);
        // rotate: C <- B, B <- A, A <- 0
#pragma unroll
        for (int nc = 0; nc < 4; nc++)
#pragma unroll
            for (int j = 0; j < 4; j++) {
                accC[nc][j] = accB[nc][j];
                accB[nc][j] = accA[nc][j];
                accA[nc][j] = 0.f;
            }
    }
    if (s_hi < dend) writeout(s_hi, accC);   // last CTA: d = NP-1
}

// ---------------------------------------------------------------------------
extern "C" void kernel_launch(void* const* d_in, const int* in_sizes, int n_in,
                              void* d_out, int out_size) {
    const float* x  = (const float*)d_in[0];
    const float* nb = (const float*)d_in[1];
    const float* cw = (const float*)d_in[2];
    const float* cb = (const float*)d_in[3];
    const float* gm = (const float*)d_in[4];
    const float* bt = (const float*)d_in[5];
    const float* mn = (const float*)d_in[6];
    const float* vr = (const float*)d_in[7];
    float* out = (float*)d_out;

    dim3 cb1(64, 4);
    dim3 cg1(HH / 4, NGRP, NDIL * BATCH);
    corr_kernel<<<cg1, cb1>>>(x, nb);

    cudaFuncSetAttribute(conv_kernel,
                         cudaFuncAttributeMaxDynamicSharedMemorySize,
                         SMEM_BYTES);
    dim3 cg2(HH / 2, NDIL * BATCH, 2);     // 32 strips x 8 x 2 d-segments
    conv_kernel<<<cg2, 128, SMEM_BYTES>>>(cw, cb, gm, bt, mn, vr, out);
}

// round 9
// speedup vs baseline: 2.9409x; 1.0418x over previous
#include <cuda_runtime.h>
#include <cstdint>

// Problem constants
#define BATCH 2
#define CHAN  128
#define NGRP  16
#define CPG   8
#define HH    64
#define WW    64
#define HW    (HH*WW)
#define NP    81
#define NDIL  4
#define NPHW  (NP*HW)

// Scratch cost volume (tf32-rounded fp32): [dil*b][g][d][h][w] ~170MB
__device__ float g_cost[(size_t)NDIL * BATCH * NGRP * NPHW];

// Conv slab geometry: per d-slice [gin(16)][row(6)][col(72)] + pad
//  GPITCH = 440 == 24 (mod 32): B-fragment banks {24k+px} all distinct ->
//  every B scalar LDS is conflict-free.
#define RPITCH 72
#define NROWS  6                  // 4 output rows + 2 halo
#define GPITCH 440                // 6*72=432, padded to 440
#define SLABF  (NGRP * GPITCH)    // 7040 floats per slice
#define NRING  2
#define NCHUNK 54                 // 27 taps x 2 gin-halves
#define WFRAGF (NCHUNK * 32 * 4)  // fragment-packed weights: 6912 floats
#define SMEM_BYTES ((NRING * SLABF + WFRAGF + 64) * 4)

// ---------------- helpers ----------------
__device__ __forceinline__ uint32_t smem_u32(const void* p) {
    uint32_t a;
    asm("{ .reg .u64 t; cvta.to.shared.u64 t, %1; cvt.u32.u64 %0, t; }"
        : "=r"(a) : "l"(p));
    return a;
}
__device__ __forceinline__ void cp_async16(uint32_t dst, const float* src) {
    asm volatile("cp.async.ca.shared.global [%0], [%1], 16;"
                 :: "r"(dst), "l"(src));
}
__device__ __forceinline__ float to_tf32(float v) {
    uint32_t t;
    asm("cvt.rna.tf32.f32 %0, %1;" : "=r"(t) : "f"(v));
    return __uint_as_float(t);
}
__device__ __forceinline__ void mma_tf32(float c[4], const uint32_t a[4],
                                         uint32_t b0, uint32_t b1) {
    asm volatile(
        "mma.sync.aligned.m16n8k8.row.col.f32.tf32.tf32.f32 "
        "{%0,%1,%2,%3}, {%4,%5,%6,%7}, {%8,%9}, {%0,%1,%2,%3};"
        : "+f"(c[0]), "+f"(c[1]), "+f"(c[2]), "+f"(c[3])
        : "r"(a[0]), "r"(a[1]), "r"(a[2]), "r"(a[3]), "r"(b0), "r"(b1));
}

// ---------------------------------------------------------------------------
// Kernel 1: grouped windowed correlation + leaky ReLU(0.1), tf32-rounded out
// ---------------------------------------------------------------------------
__global__ void corr_kernel(const float* __restrict__ x,
                            const float* __restrict__ nb) {
    const int w  = threadIdx.x;
    const int h  = blockIdx.x * 4 + threadIdx.y;
    const int g  = blockIdx.y;
    const int zb = blockIdx.z;
    const int b  = zb & 1;
    const int dil = 1 << (zb >> 1);

    float a1[CPG];
#pragma unroll
    for (int c = 0; c < CPG; c++)
        a1[c] = x[(size_t)(b * CHAN + c * NGRP + g) * HW + h * WW + w];

    const float* __restrict__ x2b = nb + (size_t)b * CHAN * HW;
    float* __restrict__ outp =
        g_cost + ((size_t)(zb * NGRP + g) * NP) * HW + h * WW + w;

#pragma unroll 1
    for (int di = 0; di < 9; di++) {
        const int y = h + (di - 4) * dil;
        const bool yok = ((unsigned)y < HH);
#pragma unroll 1
        for (int dj = 0; dj < 9; dj++) {
            const int xw = w + (dj - 4) * dil;
            float s = 0.f;
            if (yok && (unsigned)xw < WW) {
                const int off = y * WW + xw;
#pragma unroll
                for (int c = 0; c < CPG; c++)
                    s += a1[c] * x2b[(size_t)(c * NGRP + g) * HW + off];
            }
            s = (s > 0.f) ? s : 0.1f * s;
            outp[(size_t)(di * 9 + dj) * HW] = to_tf32(s);
        }
    }
}

// ---------------------------------------------------------------------------
// Kernel 2: 3x3x3 grouped conv via tf32 mma.sync, slice-streaming with
// 3 rotating accumulator sets; warp = 1 row x 64 px (nc=8) so each weight
// A-fragment load feeds 8 mma. CTA = 4 warps, tile 4 rows x 64 cols.
// grid = (16 strips, 8 zb, 2 d-segments) = 256 CTAs (one wave @ 2/SM)
// ---------------------------------------------------------------------------
__global__ void __launch_bounds__(128, 2)
conv_kernel(const float* __restrict__ conv_w,
            const float* __restrict__ conv_b,
            const float* __restrict__ bn_gamma,
            const float* __restrict__ bn_beta,
            const float* __restrict__ bn_mean,
            const float* __restrict__ bn_var,
            float* __restrict__ out) {
    extern __shared__ float sm[];
    float* s_slab = sm;                     // [NRING][SLABF]
    float* s_wf   = sm + NRING * SLABF;     // fragment-packed weights
    float* s_sc   = s_wf + WFRAGF;
    float* s_sh   = s_sc + 16;

    const int tid  = threadIdx.x;
    const int lane = tid & 31;
    const int wid  = tid >> 5;              // 0..3 = output row in tile
    const int zb   = blockIdx.y;
    const int dil_idx = zb >> 1;
    const int b    = zb & 1;
    const int h0   = blockIdx.x * 4;        // 4-row strip
    const int dseg = blockIdx.z;
    const int d0   = dseg ? 41 : 0;
    const int dend = dseg ? 81 : 41;        // [d0, dend)

    const float* __restrict__ costz = g_cost + (size_t)zb * NGRP * NPHW;

    // zero slab ring (halo/border stays zero)
    for (int i = tid; i < NRING * SLABF; i += 128) s_slab[i] = 0.f;

    // pack weights into mma A-fragment order
    {
        const float* __restrict__ wb = conv_w + (size_t)dil_idx * 16 * 16 * 27;
        for (int i = tid; i < NCHUNK * 32; i += 128) {
            int chunk = i >> 5, l = i & 31;
            int tap = chunk >> 1, half = chunk & 1;
            int g0 = l >> 2, j = l & 3;
            int gin0 = half * 8 + j;
            float4 v;
            v.x = to_tf32(wb[((g0)     * 16 + gin0)     * 27 + tap]);
            v.y = to_tf32(wb[((g0 + 8) * 16 + gin0)     * 27 + tap]);
            v.z = to_tf32(wb[((g0)     * 16 + gin0 + 4) * 27 + tap]);
            v.w = to_tf32(wb[((g0 + 8) * 16 + gin0 + 4) * 27 + tap]);
            ((float4*)s_wf)[i] = v;
        }
    }
    if (tid < NGRP) {
        int gi = dil_idx * NGRP + tid;
        float inv = bn_gamma[gi] * rsqrtf(bn_var[gi] + 1e-5f);
        s_sc[tid] = inv;
        s_sh[tid] = (conv_b[gi] - bn_mean[gi]) * inv + bn_beta[gi];
    }
    __syncthreads();

    const uint32_t slab_base = smem_u32(s_slab);
    // stage one d-slice: 16 gin x 6 rows x 16 x 16B = 1536 cp.async
    auto stage = [&](int s) {
        uint32_t dslot = slab_base + (uint32_t)((s & 1) * SLABF) * 4;
        const float* __restrict__ src0 = costz + (size_t)s * HW;
#pragma unroll
        for (int k = 0; k < 12; k++) {
            int o = tid + k * 128;
            int g = o / 96;
            int rem = o - g * 96;
            int r = rem >> 4, seg = rem & 15;
            int hg = h0 - 1 + r;
            if ((unsigned)hg < HH)
                cp_async16(dslot + (uint32_t)(g * GPITCH + r * RPITCH + 4 +
                                              seg * 4) * 4,
                           src0 + (size_t)g * NPHW + hg * WW + seg * 4);
        }
        asm volatile("cp.async.commit_group;");
    };

    const int bq = (lane & 3) * GPITCH + (lane >> 2);
    const int g0 = lane >> 2;
    const float sc0 = s_sc[g0], sh0 = s_sh[g0];
    const float sc8 = s_sc[g0 + 8], sh8 = s_sh[g0 + 8];
    const uint4* __restrict__ wf4 = (const uint4*)s_wf;

    // three rotating accumulator sets (d = s+1 / s / s-1), 8 n-chunks each
    float accA[8][4], accB[8][4], accC[8][4];
#pragma unroll
    for (int nc = 0; nc < 8; nc++)
#pragma unroll
        for (int j = 0; j < 4; j++) {
            accA[nc][j] = 0.f; accB[nc][j] = 0.f; accC[nc][j] = 0.f;
        }

    auto compute = [&](const float* slot, bool do0, bool do1, bool do2) {
#pragma unroll
        for (int kh = 0; kh < 3; kh++) {
#pragma unroll
            for (int kw = 0; kw < 3; kw++) {
#pragma unroll
                for (int half = 0; half < 2; half++) {
                    const float* baddr = slot + half * 8 * GPITCH +
                                         (wid + kh) * RPITCH +
                                         (3 + kw) + bq;
                    uint32_t B0[8], B1[8];
#pragma unroll
                    for (int nc = 0; nc < 8; nc++) {
                        B0[nc] = __float_as_uint(baddr[nc * 8]);
                        B1[nc] = __float_as_uint(baddr[nc * 8 + 4 * GPITCH]);
                    }
                    const int t2 = (kh * 3 + kw) * 2 + half;
                    if (do0) {
                        uint4 av = wf4[t2 * 32 + lane];          // kd = 0
                        uint32_t A[4] = {av.x, av.y, av.z, av.w};
#pragma unroll
                        for (int nc = 0; nc < 8; nc++)
                            mma_tf32(accA[nc], A, B0[nc], B1[nc]);
                    }
                    if (do1) {
                        uint4 av = wf4[(18 + t2) * 32 + lane];   // kd = 1
                        uint32_t A[4] = {av.x, av.y, av.z, av.w};
#pragma unroll
                        for (int nc = 0; nc < 8; nc++)
                            mma_tf32(accB[nc], A, B0[nc], B1[nc]);
                    }
                    if (do2) {
                        uint4 av = wf4[(36 + t2) * 32 + lane];   // kd = 2
                        uint32_t A[4] = {av.x, av.y, av.z, av.w};
#pragma unroll
                        for (int nc = 0; nc < 8; nc++)
                            mma_tf32(accC[nc], A, B0[nc], B1[nc]);
                    }
                }
            }
        }
    };

    const size_t obase =
        ((size_t)(b * (NDIL * NGRP) + dil_idx * NGRP) * NP) * HW +
        (size_t)(h0 + wid) * WW;
    auto writeout = [&](int d, float a[8][4]) {
        const size_t ob = obase + (size_t)d * HW;
#pragma unroll
        for (int nc = 0; nc < 8; nc++) {
            const int px = nc * 8 + (lane & 3) * 2;
            float2 v0, v1;
            v0.x = fmaxf(a[nc][0] * sc0 + sh0, 0.f);
            v0.y = fmaxf(a[nc][1] * sc0 + sh0, 0.f);
            v1.x = fmaxf(a[nc][2] * sc8 + sh8, 0.f);
            v1.y = fmaxf(a[nc][3] * sc8 + sh8, 0.f);
            *(float2*)&out[ob + (size_t)g0 * NPHW + px] = v0;
            *(float2*)&out[ob + (size_t)(g0 + 8) * NPHW + px] = v1;
        }
    };

    const int s_lo = (d0 > 0) ? d0 - 1 : 0;
    const int s_hi = (dend < NP) ? dend : NP - 1;   // inclusive

    stage(s_lo);
    stage(s_lo + 1);

#pragma unroll 1
    for (int s = s_lo; s <= s_hi; s++) {
        if (s < s_hi) asm volatile("cp.async.wait_group 1;");
        else          asm volatile("cp.async.wait_group 0;");
        __syncthreads();

        const float* slot = s_slab + (s & 1) * SLABF;
        const bool do0 = (s + 1 >= d0) && (s + 1 < dend);
        const bool do1 = (s >= d0) && (s < dend);
        const bool do2 = (s - 1 >= d0);
        if (do0 && do1 && do2)
            compute(slot, true, true, true);          // branch-free hot path
        else
            compute(slot, do0, do1, do2);

        __syncthreads();          // slot (s) reads done before staging s+2
        if (s + 2 <= s_hi) stage(s + 2);

        if (s > d0) writeout(s - 1, accC);
        // rotate: C <- B, B <- A, A <- 0
#pragma unroll
        for (int nc = 0; nc < 8; nc++)
#pragma unroll
            for (int j = 0; j < 4; j++) {
                accC[nc][j] = accB[nc][j];
                accB[nc][j] = accA[nc][j];
                accA[nc][j] = 0.f;
            }
    }
    if (s_hi < dend) writeout(s_hi, accC);   // last CTA: d = NP-1
}

// ---------------------------------------------------------------------------
extern "C" void kernel_launch(void* const* d_in, const int* in_sizes, int n_in,
                              void* d_out, int out_size) {
    const float* x  = (const float*)d_in[0];
    const float* nb = (const float*)d_in[1];
    const float* cw = (const float*)d_in[2];
    const float* cb = (const float*)d_in[3];
    const float* gm = (const float*)d_in[4];
    const float* bt = (const float*)d_in[5];
    const float* mn = (const float*)d_in[6];
    const float* vr = (const float*)d_in[7];
    float* out = (float*)d_out;

    dim3 cb1(64, 4);
    dim3 cg1(HH / 4, NGRP, NDIL * BATCH);
    corr_kernel<<<cg1, cb1>>>(x, nb);

    cudaFuncSetAttribute(conv_kernel,
                         cudaFuncAttributeMaxDynamicSharedMemorySize,
                         SMEM_BYTES);
    dim3 cg2(HH / 4, NDIL * BATCH, 2);     // 16 strips x 8 x 2 d-segments
    conv_kernel<<<cg2, 128, SMEM_BYTES>>>(cw, cb, gm, bt, mn, vr, out);
}

// round 10
// speedup vs baseline: 4.5745x; 1.5555x over previous
#include <cuda_runtime.h>
#include <cuda_fp16.h>
#include <cstdint>

// Problem constants
#define BATCH 2
#define CHAN  128
#define NGRP  16
#define CPG   8
#define HH    64
#define WW    64
#define HW    (HH*WW)
#define NP    81
#define NDIL  4
#define NPHW  (NP*HW)

// Scratch cost volume, fp16 gin-PAIR packed: [zb(8)][gp(8)][d][h][w] __half2
__device__ __half2 g_cost2[(size_t)NDIL * BATCH * (NGRP / 2) * NPHW];

// Conv slab: per d-slice [gp(8)][row(6)][col(72)] in __half2 words
//  GPW = 456 == 8 (mod 32): B-load banks = 8q + n, all distinct -> conflict-free
#define ROWW  72
#define GPW   456                  // 6*72=432 + 24 pad (half2 words)
#define SLABW (8 * GPW)            // 3648 half2 words per slice
#define NCHUNK 27                  // 27 taps (K=16 covers all gins per tap)
#define WF_BYTES (NCHUNK * 32 * 16)
#define SMEM_BYTES (2 * SLABW * 4 + WF_BYTES + 192)

// ---------------- helpers ----------------
__device__ __forceinline__ uint32_t smem_u32(const void* p) {
    uint32_t a;
    asm("{ .reg .u64 t; cvta.to.shared.u64 t, %1; cvt.u32.u64 %0, t; }"
        : "=r"(a) : "l"(p));
    return a;
}
__device__ __forceinline__ void cp_async16(uint32_t dst, const void* src) {
    asm volatile("cp.async.ca.shared.global [%0], [%1], 16;"
                 :: "r"(dst), "l"(src));
}
__device__ __forceinline__ uint32_t h2u(__half2 h) {
    return *reinterpret_cast<uint32_t*>(&h);
}
__device__ __forceinline__ void mma_f16(float c[4], const uint32_t a[4],
                                        uint32_t b0, uint32_t b1) {
    asm volatile(
        "mma.sync.aligned.m16n8k16.row.col.f32.f16.f16.f32 "
        "{%0,%1,%2,%3}, {%4,%5,%6,%7}, {%8,%9}, {%0,%1,%2,%3};"
        : "+f"(c[0]), "+f"(c[1]), "+f"(c[2]), "+f"(c[3])
        : "r"(a[0]), "r"(a[1]), "r"(a[2]), "r"(a[3]), "r"(b0), "r"(b1));
}

// ---------------------------------------------------------------------------
// Kernel 1: grouped windowed correlation + leaky ReLU(0.1), fp16-pair output
// thread computes gins (2gp, 2gp+1) for one pixel; grid (16, 8 gp, 8 zb)
// ---------------------------------------------------------------------------
__global__ void corr_kernel(const float* __restrict__ x,
                            const float* __restrict__ nb) {
    const int w  = threadIdx.x;
    const int h  = blockIdx.x * 4 + threadIdx.y;
    const int gp = blockIdx.y;               // 0..7
    const int zb = blockIdx.z;
    const int b  = zb & 1;
    const int dil = 1 << (zb >> 1);

    // x1 values: channels c*16 + 2gp (+1), c = 0..7
    float a0[CPG], a1[CPG];
#pragma unroll
    for (int c = 0; c < CPG; c++) {
        a0[c] = x[(size_t)(b * CHAN + c * NGRP + 2 * gp) * HW + h * WW + w];
        a1[c] = x[(size_t)(b * CHAN + c * NGRP + 2 * gp + 1) * HW + h * WW + w];
    }

    const float* __restrict__ x2b = nb + (size_t)b * CHAN * HW;
    __half2* __restrict__ outp =
        g_cost2 + ((size_t)(zb * 8 + gp) * NP) * HW + h * WW + w;

#pragma unroll 1
    for (int di = 0; di < 9; di++) {
        const int y = h + (di - 4) * dil;
        const bool yok = ((unsigned)y < HH);
#pragma unroll 1
        for (int dj = 0; dj < 9; dj++) {
            const int xw = w + (dj - 4) * dil;
            float s0 = 0.f, s1 = 0.f;
            if (yok && (unsigned)xw < WW) {
                const int off = y * WW + xw;
#pragma unroll
                for (int c = 0; c < CPG; c++) {
                    const float* p =
                        x2b + (size_t)(c * NGRP + 2 * gp) * HW + off;
                    s0 += a0[c] * p[0];
                    s1 += a1[c] * p[HW];
                }
            }
            s0 = (s0 > 0.f) ? s0 : 0.1f * s0;
            s1 = (s1 > 0.f) ? s1 : 0.1f * s1;
            outp[(size_t)(di * 9 + dj) * HW] =
                __float22half2_rn(make_float2(s0, s1));
        }
    }
}

// ---------------------------------------------------------------------------
// Kernel 2: 3x3x3 grouped conv via fp16 mma.sync m16n8k16, slice-streaming
// with 3 rotating fp32 accumulator sets. Warp = 1 row x 64 px.
// grid = (16 strips, 8 zb, 3 d-segments) = 384 CTAs
// ---------------------------------------------------------------------------
__global__ void __launch_bounds__(128, 3)
conv_kernel(const float* __restrict__ conv_w,
            const float* __restrict__ conv_b,
            const float* __restrict__ bn_gamma,
            const float* __restrict__ bn_beta,
            const float* __restrict__ bn_mean,
            const float* __restrict__ bn_var,
            float* __restrict__ out) {
    extern __shared__ uint32_t sm[];
    uint32_t* s_slab = sm;                          // [2][SLABW] half2 words
    uint4*    s_wf   = (uint4*)(sm + 2 * SLABW);    // [27][32] A fragments
    float*    s_sc   = (float*)(s_wf + NCHUNK * 32);
    float*    s_sh   = s_sc + 16;

    const int tid  = threadIdx.x;
    const int lane = tid & 31;
    const int wid  = tid >> 5;               // output row in tile (0..3)
    const int zb   = blockIdx.y;
    const int dil_idx = zb >> 1;
    const int b    = zb & 1;
    const int h0   = blockIdx.x * 4;
    const int dseg = blockIdx.z;
    const int d0   = dseg * 27;
    const int dend = d0 + 27;                // [d0, dend)

    const __half2* __restrict__ costz = g_cost2 + (size_t)zb * 8 * NPHW;

    // zero slab ring (halo/border stays zero forever)
    for (int i = tid; i < 2 * SLABW; i += 128) s_slab[i] = 0u;

    // pack fp16 A fragments: chunk t = kd*9+kh*3+kw; lane l: g0=l>>2, q=l&3
    // a0={W[g0][2q],W[g0][2q+1]}, a1={g0+8}, a2={k+8}, a3={g0+8,k+8}
    {
        const float* __restrict__ wb = conv_w + (size_t)dil_idx * 16 * 16 * 27;
        for (int i = tid; i < NCHUNK * 32; i += 128) {
            int t = i >> 5, l = i & 31;
            int g0 = l >> 2, k0 = (l & 3) * 2;
            uint4 v;
            v.x = h2u(__float22half2_rn(make_float2(
                wb[((g0)     * 16 + k0)     * 27 + t],
                wb[((g0)     * 16 + k0 + 1) * 27 + t])));
            v.y = h2u(__float22half2_rn(make_float2(
                wb[((g0 + 8) * 16 + k0)     * 27 + t],
                wb[((g0 + 8) * 16 + k0 + 1) * 27 + t])));
            v.z = h2u(__float22half2_rn(make_float2(
                wb[((g0)     * 16 + k0 + 8) * 27 + t],
                wb[((g0)     * 16 + k0 + 9) * 27 + t])));
            v.w = h2u(__float22half2_rn(make_float2(
                wb[((g0 + 8) * 16 + k0 + 8) * 27 + t],
                wb[((g0 + 8) * 16 + k0 + 9) * 27 + t])));
            s_wf[i] = v;
        }
    }
    if (tid < NGRP) {
        int gi = dil_idx * NGRP + tid;
        float inv = bn_gamma[gi] * rsqrtf(bn_var[gi] + 1e-5f);
        s_sc[tid] = inv;
        s_sh[tid] = (conv_b[gi] - bn_mean[gi]) * inv + bn_beta[gi];
    }
    __syncthreads();

    const uint32_t slab_base = smem_u32(s_slab);
    // stage one d-slice: 8 gp x 6 rows x 16 segs x 16B = 768 cp.async
    auto stage = [&](int s) {
        uint32_t dslot = slab_base + (uint32_t)((s & 1) * SLABW) * 4;
        const __half2* __restrict__ src0 = costz + (size_t)s * HW;
#pragma unroll
        for (int k = 0; k < 6; k++) {
            int o = tid + k * 128;            // 768 ops
            int gp = o / 96;
            int rem = o - gp * 96;
            int r = rem >> 4, seg = rem & 15;
            int hg = h0 - 1 + r;
            if ((unsigned)hg < HH)
                cp_async16(dslot + (uint32_t)(gp * GPW + r * ROWW + 4 +
                                              seg * 4) * 4,
                           src0 + (size_t)gp * NPHW + hg * WW + seg * 4);
        }
        asm volatile("cp.async.commit_group;");
    };

    // B-load lane base: gp row = q = lane&3, px-in-chunk = n = lane>>2
    const int bq = (lane & 3) * GPW + (lane >> 2);
    const int g0 = lane >> 2;
    const float sc0 = s_sc[g0], sh0 = s_sh[g0];
    const float sc8 = s_sc[g0 + 8], sh8 = s_sh[g0 + 8];

    // three rotating accumulator sets (d = s+1 / s / s-1), 8 n-chunks each
    float accA[8][4], accB[8][4], accC[8][4];
#pragma unroll
    for (int nc = 0; nc < 8; nc++)
#pragma unroll
        for (int j = 0; j < 4; j++) {
            accA[nc][j] = 0.f; accB[nc][j] = 0.f; accC[nc][j] = 0.f;
        }

    auto compute = [&](const uint32_t* slot, bool do0, bool do1, bool do2) {
#pragma unroll
        for (int kh = 0; kh < 3; kh++) {
#pragma unroll
            for (int kw = 0; kw < 3; kw++) {
                const uint32_t* baddr =
                    slot + (wid + kh) * ROWW + (3 + kw) + bq;
                uint32_t B0[8], B1[8];
#pragma unroll
                for (int nc = 0; nc < 8; nc++) {
                    B0[nc] = baddr[nc * 8];
                    B1[nc] = baddr[nc * 8 + 4 * GPW];
                }
                const int t = kh * 3 + kw;
                if (do0) {
                    uint4 av = s_wf[t * 32 + lane];            // kd = 0
                    uint32_t A[4] = {av.x, av.y, av.z, av.w};
#pragma unroll
                    for (int nc = 0; nc < 8; nc++)
                        mma_f16(accA[nc], A, B0[nc], B1[nc]);
                }
                if (do1) {
                    uint4 av = s_wf[(9 + t) * 32 + lane];      // kd = 1
                    uint32_t A[4] = {av.x, av.y, av.z, av.w};
#pragma unroll
                    for (int nc = 0; nc < 8; nc++)
                        mma_f16(accB[nc], A, B0[nc], B1[nc]);
                }
                if (do2) {
                    uint4 av = s_wf[(18 + t) * 32 + lane];     // kd = 2
                    uint32_t A[4] = {av.x, av.y, av.z, av.w};
#pragma unroll
                    for (int nc = 0; nc < 8; nc++)
                        mma_f16(accC[nc], A, B0[nc], B1[nc]);
                }
            }
        }
    };

    const size_t obase =
        ((size_t)(b * (NDIL * NGRP) + dil_idx * NGRP) * NP) * HW +
        (size_t)(h0 + wid) * WW;
    auto writeout = [&](int d, float a[8][4]) {
        const size_t ob = obase + (size_t)d * HW;
#pragma unroll
        for (int nc = 0; nc < 8; nc++) {
            const int px = nc * 8 + (lane & 3) * 2;
            float2 v0, v1;
            v0.x = fmaxf(a[nc][0] * sc0 + sh0, 0.f);
            v0.y = fmaxf(a[nc][1] * sc0 + sh0, 0.f);
            v1.x = fmaxf(a[nc][2] * sc8 + sh8, 0.f);
            v1.y = fmaxf(a[nc][3] * sc8 + sh8, 0.f);
            *(float2*)&out[ob + (size_t)g0 * NPHW + px] = v0;
            *(float2*)&out[ob + (size_t)(g0 + 8) * NPHW + px] = v1;
        }
    };

    const int s_lo = (d0 > 0) ? d0 - 1 : 0;
    const int s_hi = (dend < NP) ? dend : NP - 1;   // inclusive

    stage(s_lo);
    stage(s_lo + 1);

#pragma unroll 1
    for (int s = s_lo; s <= s_hi; s++) {
        if (s < s_hi) asm volatile("cp.async.wait_group 1;");
        else          asm volatile("cp.async.wait_group 0;");
        __syncthreads();

        const uint32_t* slot = s_slab + (s & 1) * SLABW;
        const bool do0 = (s + 1 >= d0) && (s + 1 < dend);
        const bool do1 = (s >= d0) && (s < dend);
        const bool do2 = (s - 1 >= d0);
        if (do0 && do1 && do2)
            compute(slot, true, true, true);          // branch-free hot path
        else
            compute(slot, do0, do1, do2);

        __syncthreads();          // slot (s) reads done before staging s+2
        if (s + 2 <= s_hi) stage(s + 2);

        if (s > d0) writeout(s - 1, accC);
        // rotate: C <- B, B <- A, A <- 0
#pragma unroll
        for (int nc = 0; nc < 8; nc++)
#pragma unroll
            for (int j = 0; j < 4; j++) {
                accC[nc][j] = accB[nc][j];
                accB[nc][j] = accA[nc][j];
                accA[nc][j] = 0.f;
            }
    }
    if (s_hi < dend) writeout(s_hi, accC);   // last CTA of the seg: d = NP-1
}

// ---------------------------------------------------------------------------
extern "C" void kernel_launch(void* const* d_in, const int* in_sizes, int n_in,
                              void* d_out, int out_size) {
    const float* x  = (const float*)d_in[0];
    const float* nb = (const float*)d_in[1];
    const float* cw = (const float*)d_in[2];
    const float* cb = (const float*)d_in[3];
    const float* gm = (const float*)d_in[4];
    const float* bt = (const float*)d_in[5];
    const float* mn = (const float*)d_in[6];
    const float* vr = (const float*)d_in[7];
    float* out = (float*)d_out;

    dim3 cb1(64, 4);
    dim3 cg1(HH / 4, NGRP / 2, NDIL * BATCH);
    corr_kernel<<<cg1, cb1>>>(x, nb);

    cudaFuncSetAttribute(conv_kernel,
                         cudaFuncAttributeMaxDynamicSharedMemorySize,
                         SMEM_BYTES);
    dim3 cg2(HH / 4, NDIL * BATCH, 3);     // 16 strips x 8 x 3 d-segments
    conv_kernel<<<cg2, 128, SMEM_BYTES>>>(cw, cb, gm, bt, mn, vr, out);
}

// round 11
// speedup vs baseline: 4.6727x; 1.0215x over previous
#include <cuda_runtime.h>
#include <cuda_fp16.h>
#include <cstdint>

// Problem constants
#define BATCH 2
#define CHAN  128
#define NGRP  16
#define CPG   8
#define HH    64
#define WW    64
#define HW    (HH*WW)
#define NP    81
#define NDIL  4
#define NPHW  (NP*HW)

// Scratch cost volume, fp16 gin-PAIR packed: [zb(8)][gp(8)][d][h][w] __half2
__device__ __half2 g_cost2[(size_t)NDIL * BATCH * (NGRP / 2) * NPHW];
// nb repacked to fp16 gin pairs: [b(2)][gp(8)][c(8)][h][w] __half2  (2 MB)
__device__ __half2 g_nb2[(size_t)BATCH * 8 * CPG * HW];

// Conv slab: per d-slice [gp(8)][row(6)][col(72)] in __half2 words
//  GPW = 456 == 8 (mod 32): B-load banks = 8q + n, all distinct -> conflict-free
#define ROWW  72
#define GPW   456                  // 6*72=432 + 24 pad (half2 words)
#define SLABW (8 * GPW)            // 3648 half2 words per slice
#define NCHUNK 27                  // 27 taps (K=16 covers all gins per tap)
#define WF_BYTES (NCHUNK * 32 * 16)
#define SMEM_BYTES (2 * SLABW * 4 + WF_BYTES + 192)

// ---------------- helpers ----------------
__device__ __forceinline__ uint32_t smem_u32(const void* p) {
    uint32_t a;
    asm("{ .reg .u64 t; cvta.to.shared.u64 t, %1; cvt.u32.u64 %0, t; }"
        : "=r"(a) : "l"(p));
    return a;
}
__device__ __forceinline__ void cp_async16(uint32_t dst, const void* src) {
    asm volatile("cp.async.ca.shared.global [%0], [%1], 16;"
                 :: "r"(dst), "l"(src));
}
__device__ __forceinline__ uint32_t h2u(__half2 h) {
    return *reinterpret_cast<uint32_t*>(&h);
}
__device__ __forceinline__ void mma_f16(float c[4], const uint32_t a[4],
                                        uint32_t b0, uint32_t b1) {
    asm volatile(
        "mma.sync.aligned.m16n8k16.row.col.f32.f16.f16.f32 "
        "{%0,%1,%2,%3}, {%4,%5,%6,%7}, {%8,%9}, {%0,%1,%2,%3};"
        : "+f"(c[0]), "+f"(c[1]), "+f"(c[2]), "+f"(c[3])
        : "r"(a[0]), "r"(a[1]), "r"(a[2]), "r"(a[3]), "r"(b0), "r"(b1));
}

// ---------------------------------------------------------------------------
// Kernel 0: repack nb into fp16 gin-pair planes  [b][gp][c][h][w]
// ---------------------------------------------------------------------------
__global__ void repack_kernel(const float* __restrict__ nb) {
    const int m = blockIdx.x * 256 + threadIdx.x;   // 0 .. 2^19-1
    const int p  = m & (HW - 1);
    const int c  = (m >> 12) & 7;
    const int gp = (m >> 15) & 7;
    const int b  = m >> 18;
    const float* src = nb + ((size_t)b * CHAN + c * NGRP + 2 * gp) * HW + p;
    g_nb2[m] = __floats2half2_rn(src[0], src[HW]);
}

// ---------------------------------------------------------------------------
// Kernel 1: grouped windowed correlation + leaky ReLU(0.1)
// x1 fp32, x2 fp16 gin-pairs (halves L1 read bytes), fp32 accumulate,
// fp16-pair output. grid (16, 8 gp, 8 zb), block (64,4)
// ---------------------------------------------------------------------------
__global__ void corr_kernel(const float* __restrict__ x) {
    const int w  = threadIdx.x;
    const int h  = blockIdx.x * 4 + threadIdx.y;
    const int gp = blockIdx.y;               // 0..7
    const int zb = blockIdx.z;
    const int b  = zb & 1;
    const int dil = 1 << (zb >> 1);

    // x1 values: channels c*16 + 2gp (+1), c = 0..7 (fp32)
    float a0[CPG], a1[CPG];
#pragma unroll
    for (int c = 0; c < CPG; c++) {
        a0[c] = x[(size_t)(b * CHAN + c * NGRP + 2 * gp) * HW + h * WW + w];
        a1[c] = x[(size_t)(b * CHAN + c * NGRP + 2 * gp + 1) * HW + h * WW + w];
    }

    const __half2* __restrict__ x2p =
        g_nb2 + ((size_t)b * 8 + gp) * CPG * HW;
    __half2* __restrict__ outp =
        g_cost2 + ((size_t)(zb * 8 + gp) * NP) * HW + h * WW + w;

#pragma unroll 1
    for (int di = 0; di < 9; di++) {
        const int y = h + (di - 4) * dil;
        const bool yok = ((unsigned)y < HH);
#pragma unroll 1
        for (int dj = 0; dj < 9; dj++) {
            const int xw = w + (dj - 4) * dil;
            float s0 = 0.f, s1 = 0.f;
            if (yok && (unsigned)xw < WW) {
                const int off = y * WW + xw;
#pragma unroll
                for (int c = 0; c < CPG; c++) {
                    float2 v = __half22float2(x2p[(size_t)c * HW + off]);
                    s0 += a0[c] * v.x;
                    s1 += a1[c] * v.y;
                }
            }
            s0 = (s0 > 0.f) ? s0 : 0.1f * s0;
            s1 = (s1 > 0.f) ? s1 : 0.1f * s1;
            outp[(size_t)(di * 9 + dj) * HW] =
                __float22half2_rn(make_float2(s0, s1));
        }
    }
}

// ---------------------------------------------------------------------------
// Kernel 2: 3x3x3 grouped conv via fp16 mma.sync m16n8k16, slice-streaming
// with 3 rotating fp32 accumulator sets. Warp = 1 row x 64 px.
// grid = (16 strips, 8 zb, 3 d-segments) = 384 CTAs
// ---------------------------------------------------------------------------
__global__ void __launch_bounds__(128, 3)
conv_kernel(const float* __restrict__ conv_w,
            const float* __restrict__ conv_b,
            const float* __restrict__ bn_gamma,
            const float* __restrict__ bn_beta,
            const float* __restrict__ bn_mean,
            const float* __restrict__ bn_var,
            float* __restrict__ out) {
    extern __shared__ uint32_t sm[];
    uint32_t* s_slab = sm;                          // [2][SLABW] half2 words
    uint4*    s_wf   = (uint4*)(sm + 2 * SLABW);    // [27][32] A fragments
    float*    s_sc   = (float*)(s_wf + NCHUNK * 32);
    float*    s_sh   = s_sc + 16;

    const int tid  = threadIdx.x;
    const int lane = tid & 31;
    const int wid  = tid >> 5;               // output row in tile (0..3)
    const int zb   = blockIdx.y;
    const int dil_idx = zb >> 1;
    const int b    = zb & 1;
    const int h0   = blockIdx.x * 4;
    const int dseg = blockIdx.z;
    const int d0   = dseg * 27;
    const int dend = d0 + 27;                // [d0, dend)

    const __half2* __restrict__ costz = g_cost2 + (size_t)zb * 8 * NPHW;

    // zero slab ring (halo/border stays zero forever)
    for (int i = tid; i < 2 * SLABW; i += 128) s_slab[i] = 0u;

    // pack fp16 A fragments: chunk t = kd*9+kh*3+kw; lane l: g0=l>>2, q=l&3
    {
        const float* __restrict__ wb = conv_w + (size_t)dil_idx * 16 * 16 * 27;
        for (int i = tid; i < NCHUNK * 32; i += 128) {
            int t = i >> 5, l = i & 31;
            int g0 = l >> 2, k0 = (l & 3) * 2;
            uint4 v;
            v.x = h2u(__float22half2_rn(make_float2(
                wb[((g0)     * 16 + k0)     * 27 + t],
                wb[((g0)     * 16 + k0 + 1) * 27 + t])));
            v.y = h2u(__float22half2_rn(make_float2(
                wb[((g0 + 8) * 16 + k0)     * 27 + t],
                wb[((g0 + 8) * 16 + k0 + 1) * 27 + t])));
            v.z = h2u(__float22half2_rn(make_float2(
                wb[((g0)     * 16 + k0 + 8) * 27 + t],
                wb[((g0)     * 16 + k0 + 9) * 27 + t])));
            v.w = h2u(__float22half2_rn(make_float2(
                wb[((g0 + 8) * 16 + k0 + 8) * 27 + t],
                wb[((g0 + 8) * 16 + k0 + 9) * 27 + t])));
            s_wf[i] = v;
        }
    }
    if (tid < NGRP) {
        int gi = dil_idx * NGRP + tid;
        float inv = bn_gamma[gi] * rsqrtf(bn_var[gi] + 1e-5f);
        s_sc[tid] = inv;
        s_sh[tid] = (conv_b[gi] - bn_mean[gi]) * inv + bn_beta[gi];
    }
    __syncthreads();

    const uint32_t slab_base = smem_u32(s_slab);
    // stage one d-slice: 8 gp x 6 rows x 16 segs x 16B = 768 cp.async
    auto stage = [&](int s) {
        uint32_t dslot = slab_base + (uint32_t)((s & 1) * SLABW) * 4;
        const __half2* __restrict__ src0 = costz + (size_t)s * HW;
#pragma unroll
        for (int k = 0; k < 6; k++) {
            int o = tid + k * 128;            // 768 ops
            int gp = o / 96;
            int rem = o - gp * 96;
            int r = rem >> 4, seg = rem & 15;
            int hg = h0 - 1 + r;
            if ((unsigned)hg < HH)
                cp_async16(dslot + (uint32_t)(gp * GPW + r * ROWW + 4 +
                                              seg * 4) * 4,
                           src0 + (size_t)gp * NPHW + hg * WW + seg * 4);
        }
        asm volatile("cp.async.commit_group;");
    };

    // B-load lane base: gp row = q = lane&3, px-in-chunk = n = lane>>2
    const int bq = (lane & 3) * GPW + (lane >> 2);
    const int g0 = lane >> 2;
    const float sc0 = s_sc[g0], sh0 = s_sh[g0];
    const float sc8 = s_sc[g0 + 8], sh8 = s_sh[g0 + 8];

    // three rotating accumulator sets (d = s+1 / s / s-1), 8 n-chunks each
    float accA[8][4], accB[8][4], accC[8][4];
#pragma unroll
    for (int nc = 0; nc < 8; nc++)
#pragma unroll
        for (int j = 0; j < 4; j++) {
            accA[nc][j] = 0.f; accB[nc][j] = 0.f; accC[nc][j] = 0.f;
        }

    auto compute = [&](const uint32_t* slot, bool do0, bool do1, bool do2) {
#pragma unroll
        for (int kh = 0; kh < 3; kh++) {
#pragma unroll
            for (int kw = 0; kw < 3; kw++) {
                const uint32_t* baddr =
                    slot + (wid + kh) * ROWW + (3 + kw) + bq;
                uint32_t B0[8], B1[8];
#pragma unroll
                for (int nc = 0; nc < 8; nc++) {
                    B0[nc] = baddr[nc * 8];
                    B1[nc] = baddr[nc * 8 + 4 * GPW];
                }
                const int t = kh * 3 + kw;
                if (do0) {
                    uint4 av = s_wf[t * 32 + lane];            // kd = 0
                    uint32_t A[4] = {av.x, av.y, av.z, av.w};
#pragma unroll
                    for (int nc = 0; nc < 8; nc++)
                        mma_f16(accA[nc], A, B0[nc], B1[nc]);
                }
                if (do1) {
                    uint4 av = s_wf[(9 + t) * 32 + lane];      // kd = 1
                    uint32_t A[4] = {av.x, av.y, av.z, av.w};
#pragma unroll
                    for (int nc = 0; nc < 8; nc++)
                        mma_f16(accB[nc], A, B0[nc], B1[nc]);
                }
                if (do2) {
                    uint4 av = s_wf[(18 + t) * 32 + lane];     // kd = 2
                    uint32_t A[4] = {av.x, av.y, av.z, av.w};
#pragma unroll
                    for (int nc = 0; nc < 8; nc++)
                        mma_f16(accC[nc], A, B0[nc], B1[nc]);
                }
            }
        }
    };

    const size_t obase =
        ((size_t)(b * (NDIL * NGRP) + dil_idx * NGRP) * NP) * HW +
        (size_t)(h0 + wid) * WW;
    auto writeout = [&](int d, float a[8][4]) {
        const size_t ob = obase + (size_t)d * HW;
#pragma unroll
        for (int nc = 0; nc < 8; nc++) {
            const int px = nc * 8 + (lane & 3) * 2;
            float2 v0, v1;
            v0.x = fmaxf(a[nc][0] * sc0 + sh0, 0.f);
            v0.y = fmaxf(a[nc][1] * sc0 + sh0, 0.f);
            v1.x = fmaxf(a[nc][2] * sc8 + sh8, 0.f);
            v1.y = fmaxf(a[nc][3] * sc8 + sh8, 0.f);
            *(float2*)&out[ob + (size_t)g0 * NPHW + px] = v0;
            *(float2*)&out[ob + (size_t)(g0 + 8) * NPHW + px] = v1;
        }
    };

    const int s_lo = (d0 > 0) ? d0 - 1 : 0;
    const int s_hi = (dend < NP) ? dend : NP - 1;   // inclusive

    stage(s_lo);
    stage(s_lo + 1);

#pragma unroll 1
    for (int s = s_lo; s <= s_hi; s++) {
        if (s < s_hi) asm volatile("cp.async.wait_group 1;");
        else          asm volatile("cp.async.wait_group 0;");
        __syncthreads();

        const uint32_t* slot = s_slab + (s & 1) * SLABW;
        const bool do0 = (s + 1 >= d0) && (s + 1 < dend);
        const bool do1 = (s >= d0) && (s < dend);
        const bool do2 = (s - 1 >= d0);
        if (do0 && do1 && do2)
            compute(slot, true, true, true);          // branch-free hot path
        else
            compute(slot, do0, do1, do2);

        __syncthreads();          // slot (s) reads done before staging s+2
        if (s + 2 <= s_hi) stage(s + 2);

        if (s > d0) writeout(s - 1, accC);
        // rotate: C <- B, B <- A, A <- 0
#pragma unroll
        for (int nc = 0; nc < 8; nc++)
#pragma unroll
            for (int j = 0; j < 4; j++) {
                accC[nc][j] = accB[nc][j];
                accB[nc][j] = accA[nc][j];
                accA[nc][j] = 0.f;
            }
    }
    if (s_hi < dend) writeout(s_hi, accC);   // last CTA of the seg: d = NP-1
}

// ---------------------------------------------------------------------------
extern "C" void kernel_launch(void* const* d_in, const int* in_sizes, int n_in,
                              void* d_out, int out_size) {
    const float* x  = (const float*)d_in[0];
    const float* nb = (const float*)d_in[1];
    const float* cw = (const float*)d_in[2];
    const float* cb = (const float*)d_in[3];
    const float* gm = (const float*)d_in[4];
    const float* bt = (const float*)d_in[5];
    const float* mn = (const float*)d_in[6];
    const float* vr = (const float*)d_in[7];
    float* out = (float*)d_out;

    // repack nb -> fp16 gin pairs
    repack_kernel<<<2048, 256>>>(nb);

    // correlation + leaky relu -> g_cost2 (fp16 pairs)
    dim3 cb1(64, 4);
    dim3 cg1(HH / 4, NGRP / 2, NDIL * BATCH);
    corr_kernel<<<cg1, cb1>>>(x);

    cudaFuncSetAttribute(conv_kernel,
                         cudaFuncAttributeMaxDynamicSharedMemorySize,
                         SMEM_BYTES);
    dim3 cg2(HH / 4, NDIL * BATCH, 3);     // 16 strips x 8 x 3 d-segments
    conv_kernel<<<cg2, 128, SMEM_BYTES>>>(cw, cb, gm, bt, mn, vr, out);
}